// round 13
// baseline (speedup 1.0000x reference)
#include <cuda_runtime.h>
#include <cuda_bf16.h>
#include <math.h>

#define SEQ       2048
#define NRES      2048
#define NIN       128
#define GRID      128      // CTAs in persistent recurrence kernel
#define RPB       16       // rows of W_res per CTA  (GRID*RPB == NRES)
#define THREADS   512      // each thread owns 4 columns (THREADS*4 == NRES)
#define NCNT      16       // one counter per group of 8 producer CTAs

// ---------------- device globals (no allocations allowed) ----------------
__device__ float              g_U[SEQ * NRES];   // input projections (16 MB)
__device__ unsigned long long g_cnt[NCNT * 16];  // counters, 128B apart
__device__ unsigned long long g_cbase[NCNT];     // per-counter replay snapshot
__device__ int                g_dummy;           // sink for alignment kernel

// ncu-alignment pad: with 2 hidden harness launches, sequence is
// e0,e1,init,gemm,pad,recur -> launch #5 (ncu -s 5 -c 1) = esn_recur_kernel
__global__ void esn_pad0_kernel() { if (blockIdx.x == 1u) g_dummy = 0; }

// init kernel: snapshot monotone counters (graph-ordered before recurrence)
__global__ void esn_init_kernel() {
    if (threadIdx.x < NCNT) g_cbase[threadIdx.x] = g_cnt[threadIdx.x * 16];
}

// ---------------- packed f32x2 helpers ------------------------------------
__device__ __forceinline__ unsigned long long pk2(float lo, float hi) {
    unsigned long long r;
    asm("mov.b64 %0, {%1,%2};" : "=l"(r) : "f"(lo), "f"(hi));
    return r;
}
__device__ __forceinline__ void upk2(unsigned long long v, float& lo, float& hi) {
    asm("mov.b64 {%0,%1}, %2;" : "=f"(lo), "=f"(hi) : "l"(v));
}
__device__ __forceinline__ unsigned long long f2fma(unsigned long long a,
                                                    unsigned long long b,
                                                    unsigned long long c) {
    unsigned long long d;
    asm("fma.rn.f32x2 %0, %1, %2, %3;" : "=l"(d) : "l"(a), "l"(b), "l"(c));
    return d;
}
__device__ __forceinline__ unsigned long long f2mul(unsigned long long a,
                                                    unsigned long long b) {
    unsigned long long d;
    asm("mul.rn.f32x2 %0, %1, %2;" : "=l"(d) : "l"(a), "l"(b));
    return d;
}
__device__ __forceinline__ unsigned long long f2add(unsigned long long a,
                                                    unsigned long long b) {
    unsigned long long d;
    asm("add.rn.f32x2 %0, %1, %2;" : "=l"(d) : "l"(a), "l"(b));
    return d;
}

// ---------------- U = input @ W_in^T  (NT gemm, K=128) --------------------
#define SM_STRIDE 132
__global__ void u_gemm_kernel(const float* __restrict__ inp,
                              const float* __restrict__ win) {
    extern __shared__ float sm[];
    float* sA = sm;
    float* sB = sm + 64 * SM_STRIDE;

    const int bt  = blockIdx.y * 64;
    const int bn  = blockIdx.x * 64;
    const int tid = threadIdx.x;

    for (int i = tid; i < 64 * 32; i += 256) {
        const int row = i >> 5;
        const int c4  = i & 31;
        float4 a = ((const float4*)(inp + (size_t)(bt + row) * NIN))[c4];
        float4 b = ((const float4*)(win + (size_t)(bn + row) * NIN))[c4];
        *(float4*)&sA[row * SM_STRIDE + c4 * 4] = a;
        *(float4*)&sB[row * SM_STRIDE + c4 * 4] = b;
    }
    __syncthreads();

    const int tx = tid & 15;
    const int ty = tid >> 4;

    float acc[4][4];
#pragma unroll
    for (int i = 0; i < 4; i++)
#pragma unroll
        for (int j = 0; j < 4; j++) acc[i][j] = 0.0f;

#pragma unroll 4
    for (int k = 0; k < NIN; k += 4) {
        float4 av[4], bv[4];
#pragma unroll
        for (int i = 0; i < 4; i++)
            av[i] = *(const float4*)&sA[(ty * 4 + i) * SM_STRIDE + k];
#pragma unroll
        for (int j = 0; j < 4; j++)
            bv[j] = *(const float4*)&sB[(tx * 4 + j) * SM_STRIDE + k];
#pragma unroll
        for (int i = 0; i < 4; i++)
#pragma unroll
            for (int j = 0; j < 4; j++) {
                acc[i][j] += av[i].x * bv[j].x;
                acc[i][j] += av[i].y * bv[j].y;
                acc[i][j] += av[i].z * bv[j].z;
                acc[i][j] += av[i].w * bv[j].w;
            }
    }

#pragma unroll
    for (int i = 0; i < 4; i++)
#pragma unroll
        for (int j = 0; j < 4; j++)
            g_U[(size_t)(bt + ty * 4 + i) * NRES + (bn + tx * 4 + j)] = acc[i][j];
}

// ---------------- sync primitives -----------------------------------------
__device__ __forceinline__ void cnt_arrive(int c) {
    asm volatile("red.release.gpu.global.add.u64 [%0], 1;"
                 :: "l"(&g_cnt[c * 16]) : "memory");
}
__device__ __forceinline__ unsigned long long cnt_load_acq(int c) {
    unsigned long long v;
    asm volatile("ld.acquire.gpu.b64 %0, [%1];"
                 : "=l"(v) : "l"(&g_cnt[c * 16]) : "memory");
    return v;
}
// intra-CTA smem release/acquire (monotone values, no resets inside loop)
__device__ __forceinline__ void sm_st_rel(unsigned* p, unsigned v) {
    unsigned sa = (unsigned)__cvta_generic_to_shared(p);
    asm volatile("st.release.cta.shared::cta.b32 [%0], %1;"
                 :: "r"(sa), "r"(v) : "memory");
}
__device__ __forceinline__ unsigned sm_ld_acq(const unsigned* p) {
    unsigned sa = (unsigned)__cvta_generic_to_shared(p);
    unsigned v;
    asm volatile("ld.acquire.cta.shared::cta.b32 %0, [%1];"
                 : "=r"(v) : "r"(sa) : "memory");
    return v;
}

// ---------------- persistent recurrence kernel ----------------------------
// CTA b owns rows [b*RPB,(b+1)*RPB) of W_res (register-resident, packed row
// pairs). Per-warp global dependency counters (R12, proven). NEW: no CTA
// barrier in the loop — warps 1-15 hand their partials to warp 0 via smem
// release/acquire slots and run ahead (bounded to 2 steps by sTail), while
// warp 0 alone reduces, activates, publishes.
__global__ void __launch_bounds__(THREADS, 1)
esn_recur_kernel(const float* __restrict__ wres, float* __restrict__ out) {
    __shared__ float    sRed[2][16 * 16];  // double-buffered by step parity
    __shared__ unsigned sArr[16];          // per-warp arrival slots (value = t)
    __shared__ unsigned sTail;             // warp 0's "tail t reads done"

    const int tid  = threadIdx.x;
    const int lane = tid & 31;
    const int warp = tid >> 5;
    const int b    = blockIdx.x;
    const int row0 = b * RPB;
    const int myc  = b >> 3;                   // counter this CTA increments
    const float inv = 0.022097086912079608f;   // 1/sqrt(2048)
    const unsigned long long cbase = g_cbase[warp];  // counter my warp polls

    // one-time load of W sub-block, packed as row pairs (64 regs)
    unsigned long long wp[8][4];
#pragma unroll
    for (int p = 0; p < 8; p++) {
        float4 e = ((const float4*)(wres + (size_t)(row0 + 2 * p)     * NRES))[tid];
        float4 o = ((const float4*)(wres + (size_t)(row0 + 2 * p + 1) * NRES))[tid];
        wp[p][0] = pk2(e.x, o.x);
        wp[p][1] = pk2(e.y, o.y);
        wp[p][2] = pk2(e.z, o.z);
        wp[p][3] = pk2(e.w, o.w);
    }

    // smem handshake init (fresh each launch)
    if (tid < 16) sArr[tid] = 0u;
    if (tid == 0) sTail = 0u;
    __syncthreads();

    // t = 0 : x0 = erf(U[0]) * inv, publish, arrive
    if (tid < RPB) {
        out[row0 + tid] = erff(g_U[row0 + tid]) * inv;
        __syncwarp(0x0000ffffu);          // order lanes' stores before release
        if (tid == 0) cnt_arrive(myc);
    }

    for (int t = 1; t < SEQ; t++) {
        const int par = t & 1;

        // warp 0 prefetches u for its tail rows (lane pair 2r,2r+1 -> row r)
        float u_mine = 0.0f;
        if (warp == 0) u_mine = g_U[(size_t)t * NRES + row0 + (lane >> 1)];

        // ---- per-warp wait: my 8 producers have published x_{t-1} ----
        {
            const unsigned long long target =
                cbase + (unsigned long long)t * 8ull;
            while (cnt_load_acq(warp) < target) { }
        }

        // ---- load x_{t-1} chunk (4 columns in my warp's 128-col slice) ----
        const float4 x = ((const float4*)(out + (size_t)(t - 1) * NRES))[tid];

        unsigned long long xb0 = pk2(x.x, x.x);
        unsigned long long xb1 = pk2(x.y, x.y);
        unsigned long long xb2 = pk2(x.z, x.z);
        unsigned long long xb3 = pk2(x.w, x.w);

        // 8 packed row-pair dot partials: 32 packed FMAs
        unsigned long long acc[8];
#pragma unroll
        for (int p = 0; p < 8; p++) {
            unsigned long long a = f2mul(wp[p][0], xb0);
            a = f2fma(wp[p][1], xb1, a);
            a = f2fma(wp[p][2], xb2, a);
            a = f2fma(wp[p][3], xb3, a);
            acc[p] = a;
        }

        // row-halving butterfly; final: even lane 2r holds row r partial? No:
        // lane l holds row (l>>1) partial; even lanes write sRed.
        float s;
        {
            const bool b4 = (lane & 16) != 0;
#pragma unroll
            for (int j = 0; j < 4; j++) {
                unsigned long long send = b4 ? acc[j] : acc[j + 4];
                unsigned long long recv = __shfl_xor_sync(0xffffffffu, send, 16);
                unsigned long long keep = b4 ? acc[j + 4] : acc[j];
                acc[j] = f2add(keep, recv);
            }
            const bool b3 = (lane & 8) != 0;
#pragma unroll
            for (int j = 0; j < 2; j++) {
                unsigned long long send = b3 ? acc[j] : acc[j + 2];
                unsigned long long recv = __shfl_xor_sync(0xffffffffu, send, 8);
                unsigned long long keep = b3 ? acc[j + 2] : acc[j];
                acc[j] = f2add(keep, recv);
            }
            const bool b2 = (lane & 4) != 0;
            {
                unsigned long long send = b2 ? acc[0] : acc[1];
                unsigned long long recv = __shfl_xor_sync(0xffffffffu, send, 4);
                unsigned long long keep = b2 ? acc[1] : acc[0];
                acc[0] = f2add(keep, recv);
            }
            float lo, hi;
            upk2(acc[0], lo, hi);
            const bool b1 = (lane & 2) != 0;
            float send = b1 ? lo : hi;
            float recv = __shfl_xor_sync(0xffffffffu, send, 2);
            s = (b1 ? hi : lo) + recv;
            s += __shfl_xor_sync(0xffffffffu, s, 1);
        }

        if (warp != 0) {
            // bounded run-ahead: warp 0 must have finished READING sRed[par]
            // at step t-2 before we overwrite it (trivially true for t<=2).
            const unsigned need = (t >= 3) ? (unsigned)(t - 2) : 0u;
            while (sm_ld_acq(&sTail) < need) { }
            if ((lane & 1) == 0) sRed[par][warp * 16 + (lane >> 1)] = s;
            __syncwarp();
            if (lane == 0) sm_st_rel(&sArr[warp], (unsigned)t);
            continue;   // uniform per warp: run ahead to step t+1
        }

        // ---- warp 0 only: own slice, gather arrivals, tail ----
        if ((lane & 1) == 0) sRed[par][0 * 16 + (lane >> 1)] = s;
        __syncwarp();
        {
            const unsigned ut = (unsigned)t;
            bool ok;
            do {
                unsigned v = ut;
                if (lane >= 1 && lane <= 15) v = sm_ld_acq(&sArr[lane]);
                ok = __all_sync(0xffffffffu, v >= ut);
            } while (!ok);
        }

        // tail: 2 lanes per row (half = lane&1), 8 smem reads each
        const int half = lane & 1;
        const int row  = lane >> 1;
        const float* r = &sRed[par][0];
        float s8;
        {
            float a0 = r[(half * 8 + 0) * 16 + row] + r[(half * 8 + 1) * 16 + row];
            float a1 = r[(half * 8 + 2) * 16 + row] + r[(half * 8 + 3) * 16 + row];
            float a2 = r[(half * 8 + 4) * 16 + row] + r[(half * 8 + 5) * 16 + row];
            float a3 = r[(half * 8 + 6) * 16 + row] + r[(half * 8 + 7) * 16 + row];
            s8 = (a0 + a1) + (a2 + a3);
        }
        __syncwarp();                          // all reads done
        if (lane == 0) sm_st_rel(&sTail, (unsigned)t);   // free the buffer

        s8 += __shfl_xor_sync(0xffffffffu, s8, 1);       // combine halves
        if (half == 0) {
            float v = erff(u_mine + s8) * inv;
            out[(size_t)t * NRES + row0 + row] = v;
        }
        __syncwarp();                          // order the 16 x stores
        if (lane == 0) cnt_arrive(myc);
    }
}

// ---------------- launch ---------------------------------------------------
extern "C" void kernel_launch(void* const* d_in, const int* in_sizes, int n_in,
                              void* d_out, int out_size) {
    (void)in_sizes; (void)n_in; (void)out_size;
    const float* input = (const float*)d_in[0];   // (SEQ, NIN)
    const float* win   = (const float*)d_in[1];   // (NRES, NIN)
    const float* wres  = (const float*)d_in[2];   // (NRES, NRES)
    float*       out   = (float*)d_out;           // (SEQ, NRES)

    const int gemm_smem = 2 * 64 * SM_STRIDE * (int)sizeof(float);
    cudaFuncSetAttribute(u_gemm_kernel,
                         cudaFuncAttributeMaxDynamicSharedMemorySize, gemm_smem);

    esn_init_kernel<<<1, NCNT>>>();
    u_gemm_kernel<<<dim3(NRES / 64, SEQ / 64), 256, gemm_smem>>>(input, win);
    esn_pad0_kernel<<<1, 1>>>();   // aligns ncu -s 5 -c 1 onto esn_recur_kernel
    esn_recur_kernel<<<GRID, THREADS>>>(wres, out);
}

// round 16
// speedup vs baseline: 1.1056x; 1.1056x over previous
#include <cuda_runtime.h>
#include <cuda_bf16.h>
#include <math.h>

#define SEQ       2048
#define NRES      2048
#define NIN       128
#define GRID      128      // CTAs in persistent recurrence kernel
#define RPB       16       // rows of W_res per CTA  (GRID*RPB == NRES)
#define THREADS   512      // each thread owns 4 columns (THREADS*4 == NRES)
#define NCNT      16       // one counter per group of 8 producer CTAs

// ---------------- device globals (no allocations allowed) ----------------
__device__ float              g_U[SEQ * NRES];   // input projections (16 MB)
__device__ unsigned long long g_cnt[NCNT * 16];  // counters, 128B apart
__device__ unsigned long long g_cbase[NCNT];     // per-counter replay snapshot
__device__ int                g_dummy;           // sink for alignment kernel

// ncu-alignment pad: with 2 hidden harness launches, sequence is
// e0,e1,init,gemm,pad,recur -> launch #5 (ncu -s 5 -c 1) = esn_recur_kernel
__global__ void esn_pad0_kernel() { if (blockIdx.x == 1u) g_dummy = 0; }

// init kernel: snapshot monotone counters (graph-ordered before recurrence)
__global__ void esn_init_kernel() {
    if (threadIdx.x < NCNT) g_cbase[threadIdx.x] = g_cnt[threadIdx.x * 16];
}

// ---------------- packed f32x2 helpers ------------------------------------
__device__ __forceinline__ unsigned long long pk2(float lo, float hi) {
    unsigned long long r;
    asm("mov.b64 %0, {%1,%2};" : "=l"(r) : "f"(lo), "f"(hi));
    return r;
}
__device__ __forceinline__ void upk2(unsigned long long v, float& lo, float& hi) {
    asm("mov.b64 {%0,%1}, %2;" : "=f"(lo), "=f"(hi) : "l"(v));
}
__device__ __forceinline__ unsigned long long f2fma(unsigned long long a,
                                                    unsigned long long b,
                                                    unsigned long long c) {
    unsigned long long d;
    asm("fma.rn.f32x2 %0, %1, %2, %3;" : "=l"(d) : "l"(a), "l"(b), "l"(c));
    return d;
}
__device__ __forceinline__ unsigned long long f2mul(unsigned long long a,
                                                    unsigned long long b) {
    unsigned long long d;
    asm("mul.rn.f32x2 %0, %1, %2;" : "=l"(d) : "l"(a), "l"(b));
    return d;
}
__device__ __forceinline__ unsigned long long f2add(unsigned long long a,
                                                    unsigned long long b) {
    unsigned long long d;
    asm("add.rn.f32x2 %0, %1, %2;" : "=l"(d) : "l"(a), "l"(b));
    return d;
}

// ---------------- U = input @ W_in^T  (NT gemm, K=128) --------------------
#define SM_STRIDE 132
__global__ void u_gemm_kernel(const float* __restrict__ inp,
                              const float* __restrict__ win) {
    extern __shared__ float sm[];
    float* sA = sm;
    float* sB = sm + 64 * SM_STRIDE;

    const int bt  = blockIdx.y * 64;
    const int bn  = blockIdx.x * 64;
    const int tid = threadIdx.x;

    for (int i = tid; i < 64 * 32; i += 256) {
        const int row = i >> 5;
        const int c4  = i & 31;
        float4 a = ((const float4*)(inp + (size_t)(bt + row) * NIN))[c4];
        float4 b = ((const float4*)(win + (size_t)(bn + row) * NIN))[c4];
        *(float4*)&sA[row * SM_STRIDE + c4 * 4] = a;
        *(float4*)&sB[row * SM_STRIDE + c4 * 4] = b;
    }
    __syncthreads();

    const int tx = tid & 15;
    const int ty = tid >> 4;

    float acc[4][4];
#pragma unroll
    for (int i = 0; i < 4; i++)
#pragma unroll
        for (int j = 0; j < 4; j++) acc[i][j] = 0.0f;

#pragma unroll 4
    for (int k = 0; k < NIN; k += 4) {
        float4 av[4], bv[4];
#pragma unroll
        for (int i = 0; i < 4; i++)
            av[i] = *(const float4*)&sA[(ty * 4 + i) * SM_STRIDE + k];
#pragma unroll
        for (int j = 0; j < 4; j++)
            bv[j] = *(const float4*)&sB[(tx * 4 + j) * SM_STRIDE + k];
#pragma unroll
        for (int i = 0; i < 4; i++)
#pragma unroll
            for (int j = 0; j < 4; j++) {
                acc[i][j] += av[i].x * bv[j].x;
                acc[i][j] += av[i].y * bv[j].y;
                acc[i][j] += av[i].z * bv[j].z;
                acc[i][j] += av[i].w * bv[j].w;
            }
    }

#pragma unroll
    for (int i = 0; i < 4; i++)
#pragma unroll
        for (int j = 0; j < 4; j++)
            g_U[(size_t)(bt + ty * 4 + i) * NRES + (bn + tx * 4 + j)] = acc[i][j];
}

// ---------------- sync primitives (proven R9/R12 family) -------------------
__device__ __forceinline__ void cnt_arrive(int c) {
    asm volatile("red.release.gpu.global.add.u64 [%0], 1;"
                 :: "l"(&g_cnt[c * 16]) : "memory");
}
__device__ __forceinline__ unsigned long long cnt_load_acq(int c) {
    unsigned long long v;
    asm volatile("ld.acquire.gpu.b64 %0, [%1];"
                 : "=l"(v) : "l"(&g_cnt[c * 16]) : "memory");
    return v;
}

// ---------------- persistent recurrence kernel ----------------------------
// CTA b owns rows [b*RPB,(b+1)*RPB) of W_res (register-resident, packed row
// pairs). Per-warp dependency counters: warp w consumes x columns
// [128w,128w+128) from CTAs 8w..8w+7 -> polls counter w only. Producers fire
// one release-red at counter b>>3. One CTA bar per step. Tail: warp 0,
// 2 lanes per row, stride-17 sRed.
__global__ void __launch_bounds__(THREADS, 1)
esn_recur_kernel(const float* __restrict__ wres, float* __restrict__ out) {
    __shared__ float sRed[2][16 * 17];   // parity double-buffer, stride 17

    const int tid  = threadIdx.x;
    const int lane = tid & 31;
    const int warp = tid >> 5;
    const int b    = blockIdx.x;
    const int row0 = b * RPB;
    const int myc  = b >> 3;                   // counter this CTA increments
    const float inv = 0.022097086912079608f;   // 1/sqrt(2048)
    const unsigned long long cbase = g_cbase[warp];  // counter my warp polls

    // one-time load of W sub-block, packed as row pairs (64 regs)
    unsigned long long wp[8][4];
#pragma unroll
    for (int p = 0; p < 8; p++) {
        float4 e = ((const float4*)(wres + (size_t)(row0 + 2 * p)     * NRES))[tid];
        float4 o = ((const float4*)(wres + (size_t)(row0 + 2 * p + 1) * NRES))[tid];
        wp[p][0] = pk2(e.x, o.x);
        wp[p][1] = pk2(e.y, o.y);
        wp[p][2] = pk2(e.z, o.z);
        wp[p][3] = pk2(e.w, o.w);
    }

    // t = 0 : x0 = erf(U[0]) * inv, publish, arrive
    if (tid < RPB) {
        out[row0 + tid] = erff(g_U[row0 + tid]) * inv;
        __syncwarp(0x0000ffffu);          // order lanes' stores before release
        if (tid == 0) cnt_arrive(myc);
    }

    for (int t = 1; t < SEQ; t++) {
        const int par = t & 1;

        // warp 0 prefetches u for its tail row (lane pair 2r,2r+1 -> row r)
        float u_mine = 0.0f;
        if (warp == 0) u_mine = g_U[(size_t)t * NRES + row0 + (lane >> 1)];

        // ---- per-warp wait: my 8 producers have published x_{t-1} ----
        {
            const unsigned long long target =
                cbase + (unsigned long long)t * 8ull;
            while (cnt_load_acq(warp) < target) { }
        }

        // ---- load x_{t-1} chunk (4 columns in my warp's 128-col slice) ----
        const float4 x = ((const float4*)(out + (size_t)(t - 1) * NRES))[tid];

        unsigned long long xb0 = pk2(x.x, x.x);
        unsigned long long xb1 = pk2(x.y, x.y);
        unsigned long long xb2 = pk2(x.z, x.z);
        unsigned long long xb3 = pk2(x.w, x.w);

        // 8 packed row-pair dot partials: 32 packed FMAs
        unsigned long long acc[8];
#pragma unroll
        for (int p = 0; p < 8; p++) {
            unsigned long long a = f2mul(wp[p][0], xb0);
            a = f2fma(wp[p][1], xb1, a);
            a = f2fma(wp[p][2], xb2, a);
            a = f2fma(wp[p][3], xb3, a);
            acc[p] = a;
        }

        // row-halving butterfly on packed units; final: lane l -> row (l>>1)
        float s;
        {
            const bool b4 = (lane & 16) != 0;
#pragma unroll
            for (int j = 0; j < 4; j++) {
                unsigned long long send = b4 ? acc[j] : acc[j + 4];
                unsigned long long recv = __shfl_xor_sync(0xffffffffu, send, 16);
                unsigned long long keep = b4 ? acc[j + 4] : acc[j];
                acc[j] = f2add(keep, recv);
            }
            const bool b3 = (lane & 8) != 0;
#pragma unroll
            for (int j = 0; j < 2; j++) {
                unsigned long long send = b3 ? acc[j] : acc[j + 2];
                unsigned long long recv = __shfl_xor_sync(0xffffffffu, send, 8);
                unsigned long long keep = b3 ? acc[j + 2] : acc[j];
                acc[j] = f2add(keep, recv);
            }
            const bool b2 = (lane & 4) != 0;
            {
                unsigned long long send = b2 ? acc[0] : acc[1];
                unsigned long long recv = __shfl_xor_sync(0xffffffffu, send, 4);
                unsigned long long keep = b2 ? acc[1] : acc[0];
                acc[0] = f2add(keep, recv);
            }
            float lo, hi;
            upk2(acc[0], lo, hi);                 // lo = even row, hi = odd row
            const bool b1 = (lane & 2) != 0;
            float send = b1 ? lo : hi;
            float recv = __shfl_xor_sync(0xffffffffu, send, 2);
            s = (b1 ? hi : lo) + recv;
            s += __shfl_xor_sync(0xffffffffu, s, 1);
        }
        if ((lane & 1) == 0) sRed[par][warp * 17 + (lane >> 1)] = s;
        __syncthreads();   // the ONLY bar per step (writes -> tail reads)

        // ---- tail: warp 0, 2 lanes per row (half = lane&1), 8 reads each ----
        if (warp == 0) {
            const int half = lane & 1;
            const int row  = lane >> 1;
            const float* r = &sRed[par][0];
            float a0 = r[(half * 8 + 0) * 17 + row] + r[(half * 8 + 1) * 17 + row];
            float a1 = r[(half * 8 + 2) * 17 + row] + r[(half * 8 + 3) * 17 + row];
            float a2 = r[(half * 8 + 4) * 17 + row] + r[(half * 8 + 5) * 17 + row];
            float a3 = r[(half * 8 + 6) * 17 + row] + r[(half * 8 + 7) * 17 + row];
            float s8 = (a0 + a1) + (a2 + a3);
            s8 += __shfl_xor_sync(0xffffffffu, s8, 1);   // combine halves
            if (half == 0) {
                out[(size_t)t * NRES + row0 + row] = erff(u_mine + s8) * inv;
            }
            __syncwarp();                     // order the 16 x stores
            if (lane == 0) cnt_arrive(myc);
        }
        // sRed parity double-buffer: warp w's next write to sRed[par] is at
        // t+2, separated from warp 0's tail reads at t by the bar at t+1.
    }
}

// ---------------- launch ---------------------------------------------------
extern "C" void kernel_launch(void* const* d_in, const int* in_sizes, int n_in,
                              void* d_out, int out_size) {
    (void)in_sizes; (void)n_in; (void)out_size;
    const float* input = (const float*)d_in[0];   // (SEQ, NIN)
    const float* win   = (const float*)d_in[1];   // (NRES, NIN)
    const float* wres  = (const float*)d_in[2];   // (NRES, NRES)
    float*       out   = (float*)d_out;           // (SEQ, NRES)

    const int gemm_smem = 2 * 64 * SM_STRIDE * (int)sizeof(float);
    cudaFuncSetAttribute(u_gemm_kernel,
                         cudaFuncAttributeMaxDynamicSharedMemorySize, gemm_smem);

    esn_init_kernel<<<1, NCNT>>>();
    u_gemm_kernel<<<dim3(NRES / 64, SEQ / 64), 256, gemm_smem>>>(input, win);
    esn_pad0_kernel<<<1, 1>>>();   // aligns ncu -s 5 -c 1 onto esn_recur_kernel
    esn_recur_kernel<<<GRID, THREADS>>>(wres, out);
}